// round 1
// baseline (speedup 1.0000x reference)
#include <cuda_runtime.h>
#include <cstddef>

// Shapes (fixed by the problem): B=2048, A=128, D=5, Fa=62, Fb=6, C=256, Fin=68
#define TM   64          // rows per CTA
#define HS   260         // padded smem row stride (floats); 4*HS mod 32 = 16 -> conflict-free row pairs
#define NTHR 256

#define SMEM_FLOATS (2 * TM * HS + 2 * 8 * 256)
#define SMEM_BYTES  (SMEM_FLOATS * 4)

// ---- packed f32x2 helpers (full-rate FMA path on sm_103a) ----
__device__ __forceinline__ unsigned long long dup2(float x) {
    unsigned long long r;
    asm("mov.b64 %0, {%1, %1};" : "=l"(r) : "r"(__float_as_uint(x)));
    return r;
}
__device__ __forceinline__ void ffma2(unsigned long long& d, unsigned long long a, unsigned long long b) {
    asm("fma.rn.f32x2 %0, %1, %2, %3;" : "=l"(d) : "l"(a), "l"(b), "l"(d));
}
__device__ __forceinline__ void unpack2(float& lo, float& hi, unsigned long long v) {
    unsigned int l, h;
    asm("mov.b64 {%0, %1}, %2;" : "=r"(l), "=r"(h) : "l"(v));
    lo = __uint_as_float(l); hi = __uint_as_float(h);
}

__device__ __forceinline__ float rational_act(float x, float a0, float a1, float a2, float a3,
                                              float q0, float q1, float q2) {
    float p = fmaf(fmaf(fmaf(a0, x, a1), x, a2), x, a3);
    float q = fmaf(fmaf(q0, x, q1), x, q2);   // q = 2.383 x^2 + 1 >= 1, div is safe
    return __fdividef(p, q);
}

// One fused GEMM(+bias+rational) layer operating on smem tiles.
// hin: TM x K (stride HS) in smem. hout: TM x 256 (stride HS) in smem, or (LAST) gmem out.
template<bool LAST>
__device__ __forceinline__ void layer(
    const float* __restrict__ Wg, const float* __restrict__ bg,
    int K,
    const float* __restrict__ hin, float* __restrict__ hout, float* __restrict__ Wc,
    const float* __restrict__ alpha, const float* __restrict__ beta,
    int tid, int tx, int ty,
    float* __restrict__ gout, const float* __restrict__ exist_row)
{
    unsigned long long acc[4][8];
#pragma unroll
    for (int i = 0; i < 4; i++)
#pragma unroll
        for (int j = 0; j < 8; j++) acc[i][j] = 0ull;

    const int wid  = tid >> 5;
    const int lane = tid & 31;
    const int nch  = (K + 7) >> 3;

    float4 w0, w1;
    {   // prefetch chunk 0 (warp w loads W row k0+w, 8 floats per lane)
        int krow = wid;
        if (krow < K) {
            const float4* p = (const float4*)(Wg + (size_t)krow * 256 + lane * 8);
            w0 = p[0]; w1 = p[1];
        } else { w0 = make_float4(0.f,0.f,0.f,0.f); w1 = w0; }
    }

    for (int c = 0; c < nch; ++c) {
        float* wbuf = Wc + (c & 1) * (8 * 256);
        float4* sp = (float4*)(wbuf + wid * 256 + lane * 8);
        sp[0] = w0; sp[1] = w1;
        __syncthreads();                       // single sync per chunk (double buffered)

        if (c + 1 < nch) {                     // prefetch next chunk into regs
            int krow = (c + 1) * 8 + wid;
            if (krow < K) {
                const float4* p = (const float4*)(Wg + (size_t)krow * 256 + lane * 8);
                w0 = p[0]; w1 = p[1];
            } else { w0 = make_float4(0.f,0.f,0.f,0.f); w1 = w0; }
        }

        const int kbase = c * 8;
#pragma unroll
        for (int kk = 0; kk < 8; ++kk) {
            unsigned long long hv[4];
#pragma unroll
            for (int i = 0; i < 4; i++)
                hv[i] = dup2(hin[(ty * 4 + i) * HS + kbase + kk]);
#pragma unroll
            for (int j = 0; j < 8; j++) {
                unsigned long long wv =
                    *(const unsigned long long*)(wbuf + kk * 256 + 2 * (tx + 16 * j));
#pragma unroll
                for (int i = 0; i < 4; i++) ffma2(acc[i][j], hv[i], wv);
            }
        }
        __syncthreads();                       // wbuf consumed; safe to refill either buffer
    }

    // epilogue: bias + rational activation (+ existence mask & gmem store on last layer)
    const float a0 = alpha[0], a1 = alpha[1], a2 = alpha[2], a3 = alpha[3];
    const float q0 = beta[0],  q1 = beta[1],  q2 = beta[2];

#pragma unroll
    for (int i = 0; i < 4; i++) {
        const int r = ty * 4 + i;
        float ex = 1.f;
        if (LAST) ex = exist_row[r];
#pragma unroll
        for (int j = 0; j < 8; j++) {
            const int col = 2 * (tx + 16 * j);
            float x0, x1;
            unpack2(x0, x1, acc[i][j]);
            x0 += bg[col]; x1 += bg[col + 1];
            x0 = rational_act(x0, a0, a1, a2, a3, q0, q1, q2);
            x1 = rational_act(x1, a0, a1, a2, a3, q0, q1, q2);
            if (LAST) {
                x0 *= ex; x1 *= ex;
                *(float2*)(gout + (size_t)r * 256 + col) = make_float2(x0, x1);
            } else {
                *(float2*)(&hout[r * HS + col]) = make_float2(x0, x1);
            }
        }
    }
    // no sync needed here: next layer's first chunk sync orders hout writes vs reads
}

__global__ __launch_bounds__(NTHR, 1)
void drnfh_fused_kernel(const float* __restrict__ atoms,
                        const float* __restrict__ bonds,
                        const int*   __restrict__ edges,
                        const float* __restrict__ exist,
                        const float* __restrict__ W1, const float* __restrict__ b1,
                        const float* __restrict__ W2, const float* __restrict__ b2,
                        const float* __restrict__ W3, const float* __restrict__ b3,
                        const float* __restrict__ W4, const float* __restrict__ b4,
                        const float* __restrict__ W5, const float* __restrict__ b5,
                        const float* __restrict__ alphas, const float* __restrict__ betas,
                        float* __restrict__ out)
{
    extern __shared__ float smem[];
    float* hA = smem;                  // TM * HS
    float* hB = hA + TM * HS;          // TM * HS
    float* Wc = hB + TM * HS;          // 2 * 8 * 256

    const int tid = threadIdx.x;
    const int tx  = tid & 15;
    const int ty  = tid >> 4;
    const int m0  = blockIdx.x * TM;   // global row base; TM=64 stays inside one batch
    const int batch = m0 >> 7;         // A = 128
    const int abase = m0 & 127;

    // ---- h0 = [atoms + sum(neigh atoms), sum(bonds)] into hA, cols 68..71 zero-padded
    {
        const float* atom_b = atoms + (size_t)batch * 128 * 62;
        const float* bond_b = bonds + (size_t)batch * 128 * 5 * 6;
        const int*   edge_b = edges + (size_t)batch * 128 * 5;
        for (int idx = tid; idx < TM * 72; idx += NTHR) {
            const int r = idx / 72;
            const int f = idx - r * 72;
            const int a = abase + r;
            float v = 0.f;
            if (f < 62) {
                v = atom_b[a * 62 + f];
#pragma unroll
                for (int d = 0; d < 5; d++) {
                    const int e = edge_b[a * 5 + d];
                    if (e >= 0) v += atom_b[e * 62 + f];   // e == -1 marks padding -> contributes 0
                }
            } else if (f < 68) {
                const int fb = f - 62;
#pragma unroll
                for (int d = 0; d < 5; d++)
                    v += bond_b[(a * 5 + d) * 6 + fb];
            }
            hA[r * HS + f] = v;
        }
    }
    // ordering vs. layer-1 compute is provided by the first chunk __syncthreads inside layer()

    float* gout = out + (size_t)m0 * 256;
    const float* exr = exist + m0;

    layer<false>(W1, b1,  68, hA, hB, Wc, alphas + 0,  betas + 0, tid, tx, ty, gout, exr);
    layer<false>(W2, b2, 256, hB, hA, Wc, alphas + 4,  betas + 3, tid, tx, ty, gout, exr);
    layer<false>(W3, b3, 256, hA, hB, Wc, alphas + 8,  betas + 6, tid, tx, ty, gout, exr);
    layer<false>(W4, b4, 256, hB, hA, Wc, alphas + 12, betas + 9, tid, tx, ty, gout, exr);
    layer<true >(W5, b5, 256, hA, hB, Wc, alphas + 16, betas + 12, tid, tx, ty, gout, exr);
}

extern "C" void kernel_launch(void* const* d_in, const int* in_sizes, int n_in,
                              void* d_out, int out_size)
{
    const float* atoms = (const float*)d_in[0];
    const float* bonds = (const float*)d_in[1];
    const int*   edges = (const int*)  d_in[2];
    const float* exist = (const float*)d_in[3];
    const float* W1 = (const float*)d_in[4];
    const float* b1 = (const float*)d_in[5];
    const float* W2 = (const float*)d_in[6];
    const float* b2 = (const float*)d_in[7];
    const float* W3 = (const float*)d_in[8];
    const float* b3 = (const float*)d_in[9];
    const float* W4 = (const float*)d_in[10];
    const float* b4 = (const float*)d_in[11];
    const float* W5 = (const float*)d_in[12];
    const float* b5 = (const float*)d_in[13];
    const float* alphas = (const float*)d_in[14];
    const float* betas  = (const float*)d_in[15];
    float* out = (float*)d_out;

    const int M = out_size / 256;          // 262144 rows
    const int grid = M / TM;               // 4096 CTAs

    cudaFuncSetAttribute(drnfh_fused_kernel,
                         cudaFuncAttributeMaxDynamicSharedMemorySize, SMEM_BYTES);
    drnfh_fused_kernel<<<grid, NTHR, SMEM_BYTES>>>(
        atoms, bonds, edges, exist,
        W1, b1, W2, b2, W3, b3, W4, b4, W5, b5,
        alphas, betas, out);
}

// round 3
// speedup vs baseline: 2.4279x; 2.4279x over previous
#include <cuda_runtime.h>
#include <cuda_bf16.h>
#include <cstdint>
#include <cstddef>

// Shapes fixed: B=2048, A=128, D=5, Fa=62, Fb=6, C=256, Fin=68 (pad K0 to 80)
#define NT 512

// dynamic smem layout (bytes)
#define AHI_OFF  0          // A hi fragment plane: [8 mt][16 kt][32 lane][16B] = 64KB
#define ALO_OFF  65536      // A lo fragment plane: 64KB
#define WBUF_OFF 131072     // W chunks: 2 buffers x 32KB
#define WBUF_SZ  32768
#define SMEM_BYTES 196608
#define HSTRIDE 80          // h0 staging row stride (floats), overlays WBUF region

#define NCHUNK 35           // layer0: 3 chunks (5 kt), layers1-4: 8 chunks (16 kt) each

// weights in B-fragment order: [plane(hi/lo)][layer(5)][kt(16)][nt(32)][lane(32)][2 x u32]
__device__ __align__(16) uint32_t g_W[2*5*16*32*32*2];

// ---------------- helpers ----------------
static __device__ __forceinline__ uint32_t smem_u32(const void* p){
    uint32_t a;
    asm("{ .reg .u64 t; cvta.to.shared.u64 t, %1; cvt.u32.u64 %0, t; }" : "=r"(a) : "l"(p));
    return a;
}

// pack (x -> low half, y -> high half) and produce hi/lo bf16x2 split
static __device__ __forceinline__ void split2(float x, float y, uint32_t& h, uint32_t& l){
    asm("cvt.rn.bf16x2.f32 %0, %1, %2;" : "=r"(h) : "f"(y), "f"(x));
    float hx = __uint_as_float(h << 16);
    float hy = __uint_as_float(h & 0xffff0000u);
    float lx = x - hx, ly = y - hy;
    asm("cvt.rn.bf16x2.f32 %0, %1, %2;" : "=r"(l) : "f"(ly), "f"(lx));
}

#define MMA(d, a, b0, b1) \
    asm volatile("mma.sync.aligned.m16n8k16.row.col.f32.bf16.bf16.f32 " \
        "{%0,%1,%2,%3}, {%4,%5,%6,%7}, {%8,%9}, {%0,%1,%2,%3};" \
        : "+f"((d)[0]),"+f"((d)[1]),"+f"((d)[2]),"+f"((d)[3]) \
        : "r"((a)[0]),"r"((a)[1]),"r"((a)[2]),"r"((a)[3]), "r"(b0),"r"(b1))

#define LDS128(v, addr) \
    asm volatile("ld.shared.v4.b32 {%0,%1,%2,%3}, [%4];" \
        : "=r"((v)[0]),"=r"((v)[1]),"=r"((v)[2]),"=r"((v)[3]) : "r"(addr))

#define STS128(addr, v) \
    asm volatile("st.shared.v4.b32 [%0], {%1,%2,%3,%4};" \
        :: "r"(addr), "r"((v)[0]),"r"((v)[1]),"r"((v)[2]),"r"((v)[3]))

#define LDS64(b0, b1, addr) \
    asm volatile("ld.shared.v2.b32 {%0,%1}, [%2];" : "=r"(b0),"=r"(b1) : "r"(addr))

static __device__ __forceinline__ float ract(float x, float a0, float a1, float a2, float a3,
                                             float q0, float q1, float q2){
    float p = fmaf(fmaf(fmaf(a0, x, a1), x, a2), x, a3);
    float q = fmaf(fmaf(q0, x, q1), x, q2);    // q = 2.383 x^2 + 1 >= 1
    return __fdividef(p, q);
}

static __device__ __forceinline__ void chunk_map(int g, int& l, int& kt0, int& nkt){
    if (g < 3){ l = 0; kt0 = 2*g; nkt = (g == 2) ? 1 : 2; }
    else { int r = g - 3; l = 1 + (r >> 3); kt0 = (r & 7) * 2; nkt = 2; }
}

static __device__ __forceinline__ void issue_chunk(int g, uint32_t sb, int tid){
    int l, kt0, nkt; chunk_map(g, l, kt0, nkt);
    const uint32_t wb = sb + WBUF_OFF + (uint32_t)(g & 1) * WBUF_SZ;
#pragma unroll
    for (int i = 0; i < 4; i++){
        int u = tid + 512 * i;                 // 2048 16B units per chunk
        int plane = u >> 10;
        int ktl   = (u >> 9) & 1;
        int rest  = u & 511;
        int kt    = kt0 + ktl;                 // may exceed nkt on layer0 tail; array still valid
        const char* gp = (const char*)g_W +
            ((size_t)(((plane * 5 + l) * 16 + kt)) * 512 + rest) * 16;
        uint32_t sp = wb + (uint32_t)(((plane * 2 + ktl) * 512 + rest) * 16);
        asm volatile("cp.async.ca.shared.global [%0], [%1], 16;" :: "r"(sp), "l"(gp));
    }
    asm volatile("cp.async.commit_group;" ::: "memory");
}

// ---------------- prep: W -> split bf16 B-fragment planes ----------------
__global__ void prep_kernel(const float* __restrict__ W1, const float* __restrict__ W2,
                            const float* __restrict__ W3, const float* __restrict__ W4,
                            const float* __restrict__ W5)
{
    int i = blockIdx.x * blockDim.x + threadIdx.x;   // 5*16*32*32 = 81920
    if (i >= 5*16*32*32) return;
    const int lane = i & 31;
    const int nt   = (i >> 5) & 31;
    const int kt   = (i >> 10) & 15;
    const int l    = i >> 14;
    const float* W = (l == 0) ? W1 : (l == 1) ? W2 : (l == 2) ? W3 : (l == 3) ? W4 : W5;
    const int Kr = (l == 0) ? 68 : 256;
    const int tig = lane & 3, gid = lane >> 2;
    const int n  = nt * 8 + gid;
    const int k0 = kt * 16 + 2 * tig;

    float v[4];
#pragma unroll
    for (int r = 0; r < 4; r++){
        int k = k0 + (r >> 1) * 8 + (r & 1);         // k0, k0+1, k0+8, k0+9
        v[r] = (k < Kr) ? W[k * 256 + n] : 0.f;
    }
    uint32_t bh0, bl0, bh1, bl1;
    split2(v[0], v[1], bh0, bl0);
    split2(v[2], v[3], bh1, bl1);

    const size_t base = ((size_t)(((0*5 + l) * 16 + kt) * 32 + nt) * 32 + lane) * 2;
    const size_t pstep = (size_t)5*16*32*32*2;
    g_W[base]     = bh0;  g_W[base + 1]     = bh1;
    g_W[base + pstep] = bl0;  g_W[base + pstep + 1] = bl1;
}

// ---------------- main fused kernel ----------------
__global__ __launch_bounds__(NT, 1)
void drnfh_mma_kernel(const float* __restrict__ atoms,
                      const float* __restrict__ bonds,
                      const int*   __restrict__ edges,
                      const float* __restrict__ exist,
                      const float* __restrict__ b1, const float* __restrict__ b2,
                      const float* __restrict__ b3, const float* __restrict__ b4,
                      const float* __restrict__ b5,
                      const float* __restrict__ alphas, const float* __restrict__ betas,
                      float* __restrict__ out)
{
    extern __shared__ char smem[];
    const uint32_t sb = smem_u32(smem);
    float* hst = (float*)(smem + WBUF_OFF);         // h0 staging overlays W region

    const int tid  = threadIdx.x;
    const int lane = tid & 31;
    const int wid  = tid >> 5;
    const int wr   = wid >> 2;                      // warp row 0..3 (32 m-rows each)
    const int wc   = wid & 3;                       // warp col 0..3 (64 n-cols each)
    const int tig  = lane & 3;
    const int gid  = lane >> 2;
    const int t    = blockIdx.x;                    // one batch per CTA

    // ---- build h0 fp32 (128 x 80, zero-padded) ----
    {
        const float* atom_b = atoms + (size_t)t * 128 * 62;
        const float* bond_b = bonds + (size_t)t * 128 * 30;
        const int*   edge_b = edges + (size_t)t * 128 * 5;
        for (int idx = tid; idx < 128 * 80; idx += NT){
            const int r = idx / 80;
            const int f = idx - r * 80;
            float v = 0.f;
            if (f < 62){
                v = atom_b[r * 62 + f];
#pragma unroll
                for (int d = 0; d < 5; d++){
                    const int e = edge_b[r * 5 + d];
                    if (e >= 0) v += atom_b[e * 62 + f];
                }
            } else if (f < 68){
                const int fb = f - 62;
#pragma unroll
                for (int d = 0; d < 5; d++)
                    v += bond_b[(r * 5 + d) * 6 + fb];
            }
            hst[r * HSTRIDE + f] = v;
        }
    }
    __syncthreads();

    // ---- split h0 into A fragment planes (mt 0..7, kt 0..4) ----
    for (int task = wid; task < 40; task += 16){
        const int mt = task / 5;
        const int kt = task - mt * 5;
        const int r0 = mt * 16 + gid;
        const int c0 = kt * 16 + 2 * tig;
        float2 x0 = *(const float2*)&hst[r0 * HSTRIDE + c0];
        float2 x1 = *(const float2*)&hst[(r0 + 8) * HSTRIDE + c0];
        float2 x2 = *(const float2*)&hst[r0 * HSTRIDE + c0 + 8];
        float2 x3 = *(const float2*)&hst[(r0 + 8) * HSTRIDE + c0 + 8];
        uint32_t ah[4], al[4];
        split2(x0.x, x0.y, ah[0], al[0]);
        split2(x1.x, x1.y, ah[1], al[1]);
        split2(x2.x, x2.y, ah[2], al[2]);
        split2(x3.x, x3.y, ah[3], al[3]);
        const uint32_t off = (uint32_t)(((mt * 16 + kt) * 32 + lane) * 16);
        STS128(sb + AHI_OFF + off, ah);
        STS128(sb + ALO_OFF + off, al);
    }
    __syncthreads();

    // ---- flat chunked mainloop over all 5 layers ----
    issue_chunk(0, sb, tid);

    const float* bs[5] = { b1, b2, b3, b4, b5 };
    float acc[2][8][4];

    for (int g = 0; g < NCHUNK; g++){
        int l, kt0, nkt; chunk_map(g, l, kt0, nkt);
        asm volatile("cp.async.wait_group 0;" ::: "memory");
        __syncthreads();
        if (g + 1 < NCHUNK) issue_chunk(g + 1, sb, tid);

        if (kt0 == 0){
#pragma unroll
            for (int i = 0; i < 2; i++)
#pragma unroll
                for (int j = 0; j < 8; j++)
#pragma unroll
                    for (int r = 0; r < 4; r++) acc[i][j][r] = 0.f;
        }

        const uint32_t wb = sb + WBUF_OFF + (uint32_t)(g & 1) * WBUF_SZ;
        for (int ktl = 0; ktl < nkt; ktl++){
            const int kt = kt0 + ktl;
            uint32_t ah0[4], ah1[4], al0[4], al1[4];
            const uint32_t ao0 = (uint32_t)((((2*wr    ) * 16 + kt) * 32 + lane) * 16);
            const uint32_t ao1 = (uint32_t)((((2*wr + 1) * 16 + kt) * 32 + lane) * 16);
            LDS128(ah0, sb + AHI_OFF + ao0);
            LDS128(ah1, sb + AHI_OFF + ao1);
            LDS128(al0, sb + ALO_OFF + ao0);
            LDS128(al1, sb + ALO_OFF + ao1);
#pragma unroll
            for (int j = 0; j < 8; j++){
                const int nt = 8 * wc + j;
                uint32_t bh0, bh1, bl0, bl1;
                const uint32_t bo = (uint32_t)((ktl * 1024 + nt * 32 + lane) * 8);
                LDS64(bh0, bh1, wb + bo);
                LDS64(bl0, bl1, wb + (uint32_t)(2 * 1024 * 8) + bo);
                MMA(acc[0][j], ah0, bh0, bh1);
                MMA(acc[1][j], ah1, bh0, bh1);
                MMA(acc[0][j], al0, bh0, bh1);
                MMA(acc[1][j], al1, bh0, bh1);
                MMA(acc[0][j], ah0, bl0, bl1);
                MMA(acc[1][j], ah1, bl0, bl1);
            }
        }

        const bool layer_end = (l == 0) ? (g == 2) : (((g - 3) & 7) == 7);
        if (layer_end){
            __syncthreads();   // all warps done reading A planes
            const float* bp = bs[l];
            const float a0 = __ldg(alphas + l*4 + 0), a1 = __ldg(alphas + l*4 + 1);
            const float a2 = __ldg(alphas + l*4 + 2), a3 = __ldg(alphas + l*4 + 3);
            const float q0 = __ldg(betas + l*3 + 0),  q1 = __ldg(betas + l*3 + 1);
            const float q2 = __ldg(betas + l*3 + 2);

            if (l < 4){
#pragma unroll
                for (int mt = 0; mt < 2; mt++){
#pragma unroll
                    for (int jj = 0; jj < 8; jj += 2){
                        float x[8];
#pragma unroll
                        for (int p = 0; p < 2; p++){
                            const int n0 = (8 * wc + jj + p) * 8 + 2 * tig;
                            const float2 bb = *(const float2*)(bp + n0);
                            x[p*4+0] = ract(acc[mt][jj+p][0] + bb.x, a0,a1,a2,a3, q0,q1,q2);
                            x[p*4+1] = ract(acc[mt][jj+p][1] + bb.y, a0,a1,a2,a3, q0,q1,q2);
                            x[p*4+2] = ract(acc[mt][jj+p][2] + bb.x, a0,a1,a2,a3, q0,q1,q2);
                            x[p*4+3] = ract(acc[mt][jj+p][3] + bb.y, a0,a1,a2,a3, q0,q1,q2);
                        }
                        uint32_t ah[4], al[4];
                        split2(x[0], x[1], ah[0], al[0]);   // a0: (row gid,  cols 2tig..)
                        split2(x[2], x[3], ah[1], al[1]);   // a1: (row gid+8)
                        split2(x[4], x[5], ah[2], al[2]);   // a2: cols +8
                        split2(x[6], x[7], ah[3], al[3]);   // a3
                        const int ktn = 4 * wc + (jj >> 1);
                        const uint32_t off =
                            (uint32_t)((((2*wr + mt) * 16 + ktn) * 32 + lane) * 16);
                        STS128(sb + AHI_OFF + off, ah);
                        STS128(sb + ALO_OFF + off, al);
                    }
                }
                __syncthreads();   // A planes ready for next layer
            } else {
#pragma unroll
                for (int mt = 0; mt < 2; mt++){
                    const int r0 = (2*wr + mt) * 16 + gid;
                    const float e0 = exist[t * 128 + r0];
                    const float e1 = exist[t * 128 + r0 + 8];
#pragma unroll
                    for (int j = 0; j < 8; j++){
                        const int n0 = (8 * wc + j) * 8 + 2 * tig;
                        const float2 bb = *(const float2*)(bp + n0);
                        float y0 = ract(acc[mt][j][0] + bb.x, a0,a1,a2,a3, q0,q1,q2) * e0;
                        float y1 = ract(acc[mt][j][1] + bb.y, a0,a1,a2,a3, q0,q1,q2) * e0;
                        float y2 = ract(acc[mt][j][2] + bb.x, a0,a1,a2,a3, q0,q1,q2) * e1;
                        float y3 = ract(acc[mt][j][3] + bb.y, a0,a1,a2,a3, q0,q1,q2) * e1;
                        *(float2*)(out + ((size_t)t * 128 + r0) * 256 + n0)     = make_float2(y0, y1);
                        *(float2*)(out + ((size_t)t * 128 + r0 + 8) * 256 + n0) = make_float2(y2, y3);
                    }
                }
            }
        }
    }
}

extern "C" void kernel_launch(void* const* d_in, const int* in_sizes, int n_in,
                              void* d_out, int out_size)
{
    const float* atoms = (const float*)d_in[0];
    const float* bonds = (const float*)d_in[1];
    const int*   edges = (const int*)  d_in[2];
    const float* exist = (const float*)d_in[3];
    const float* W1 = (const float*)d_in[4];
    const float* b1 = (const float*)d_in[5];
    const float* W2 = (const float*)d_in[6];
    const float* b2 = (const float*)d_in[7];
    const float* W3 = (const float*)d_in[8];
    const float* b3 = (const float*)d_in[9];
    const float* W4 = (const float*)d_in[10];
    const float* b4 = (const float*)d_in[11];
    const float* W5 = (const float*)d_in[12];
    const float* b5 = (const float*)d_in[13];
    const float* alphas = (const float*)d_in[14];
    const float* betas  = (const float*)d_in[15];
    float* out = (float*)d_out;

    const int M = out_size / 256;     // 262144 rows
    const int T = M / 128;            // 2048 CTAs

    prep_kernel<<<(5*16*32*32 + 255) / 256, 256>>>(W1, W2, W3, W4, W5);

    cudaFuncSetAttribute(drnfh_mma_kernel,
                         cudaFuncAttributeMaxDynamicSharedMemorySize, SMEM_BYTES);
    drnfh_mma_kernel<<<T, NT, SMEM_BYTES>>>(
        atoms, bonds, edges, exist,
        b1, b2, b3, b4, b5, alphas, betas, out);
}

// round 4
// speedup vs baseline: 2.8252x; 1.1636x over previous
#include <cuda_runtime.h>
#include <cuda_bf16.h>
#include <cstdint>
#include <cstddef>

// Shapes fixed: B=2048, A=128, D=5, Fa=62, Fb=6, C=256, Fin=68 (pad K0 to 80)
// CTA tile: M=64, N=256. 2 CTAs/SM.
#define NT 256

// dynamic smem layout (bytes)
#define AHI_OFF  0            // A hi plane: [4 mt][16 kt][32 lane][16B] = 32KB
#define ALO_OFF  32768        // A lo plane: 32KB
#define WBUF_OFF 65536        // 3 x 16KB chunk buffers
#define WBUF_SZ  16384
#define SMEM_BYTES (65536 + 3*16384)   // 114688 = 112KB -> 2 CTAs/SM
#define HSTRIDE 80            // h0 staging row stride (floats), overlays WBUF

#define NCHUNK 69             // layer0: 5 kt, layers1-4: 16 kt each

// weights in B-fragment order: [plane(hi/lo)][layer(5)][kt(16)][nt(32)][lane(32)][2 x u32]
__device__ __align__(16) uint32_t g_W[2*5*16*32*32*2];

// ---------------- helpers ----------------
static __device__ __forceinline__ uint32_t smem_u32(const void* p){
    uint32_t a;
    asm("{ .reg .u64 t; cvta.to.shared.u64 t, %1; cvt.u32.u64 %0, t; }" : "=r"(a) : "l"(p));
    return a;
}

static __device__ __forceinline__ void split2(float x, float y, uint32_t& h, uint32_t& l){
    asm("cvt.rn.bf16x2.f32 %0, %1, %2;" : "=r"(h) : "f"(y), "f"(x));
    float hx = __uint_as_float(h << 16);
    float hy = __uint_as_float(h & 0xffff0000u);
    float lx = x - hx, ly = y - hy;
    asm("cvt.rn.bf16x2.f32 %0, %1, %2;" : "=r"(l) : "f"(ly), "f"(lx));
}

#define MMA(d, a, b0, b1) \
    asm volatile("mma.sync.aligned.m16n8k16.row.col.f32.bf16.bf16.f32 " \
        "{%0,%1,%2,%3}, {%4,%5,%6,%7}, {%8,%9}, {%0,%1,%2,%3};" \
        : "+f"((d)[0]),"+f"((d)[1]),"+f"((d)[2]),"+f"((d)[3]) \
        : "r"((a)[0]),"r"((a)[1]),"r"((a)[2]),"r"((a)[3]), "r"(b0),"r"(b1))

#define LDS128(v, addr) \
    asm volatile("ld.shared.v4.b32 {%0,%1,%2,%3}, [%4];" \
        : "=r"((v)[0]),"=r"((v)[1]),"=r"((v)[2]),"=r"((v)[3]) : "r"(addr))

#define STS128(addr, v) \
    asm volatile("st.shared.v4.b32 [%0], {%1,%2,%3,%4};" \
        :: "r"(addr), "r"((v)[0]),"r"((v)[1]),"r"((v)[2]),"r"((v)[3]))

#define LDS64(b0, b1, addr) \
    asm volatile("ld.shared.v2.b32 {%0,%1}, [%2];" : "=r"(b0),"=r"(b1) : "r"(addr))

static __device__ __forceinline__ float ract(float x, float a0, float a1, float a2, float a3,
                                             float q0, float q1, float q2){
    float p = fmaf(fmaf(fmaf(a0, x, a1), x, a2), x, a3);
    float q = fmaf(fmaf(q0, x, q1), x, q2);    // q = 2.383 x^2 + 1 >= 1
    return __fdividef(p, q);
}

static __device__ __forceinline__ void chunk_map(int g, int& l, int& kt){
    if (g < 5){ l = 0; kt = g; }
    else { int r = g - 5; l = 1 + (r >> 4); kt = r & 15; }
}

static __device__ __forceinline__ void issue_chunk(int g, uint32_t sb, int tid){
    int l, kt; chunk_map(g, l, kt);
    const uint32_t wb = sb + WBUF_OFF + (uint32_t)(g % 3) * WBUF_SZ;
#pragma unroll
    for (int i = 0; i < 4; i++){
        int u = tid + NT * i;                  // 1024 16B units per chunk (16KB)
        int plane = u >> 9;
        int rest  = u & 511;
        const char* gp = (const char*)g_W +
            ((size_t)(((plane * 5 + l) * 16 + kt)) * 512 + rest) * 16;
        uint32_t sp = wb + (uint32_t)((plane * 512 + rest) * 16);
        asm volatile("cp.async.ca.shared.global [%0], [%1], 16;" :: "r"(sp), "l"(gp));
    }
    asm volatile("cp.async.commit_group;" ::: "memory");
}

// ---------------- prep: W -> split bf16 B-fragment planes ----------------
__global__ void prep_kernel(const float* __restrict__ W1, const float* __restrict__ W2,
                            const float* __restrict__ W3, const float* __restrict__ W4,
                            const float* __restrict__ W5)
{
    int i = blockIdx.x * blockDim.x + threadIdx.x;   // 5*16*32*32 = 81920
    if (i >= 5*16*32*32) return;
    const int lane = i & 31;
    const int nt   = (i >> 5) & 31;
    const int kt   = (i >> 10) & 15;
    const int l    = i >> 14;
    const float* W = (l == 0) ? W1 : (l == 1) ? W2 : (l == 2) ? W3 : (l == 3) ? W4 : W5;
    const int Kr = (l == 0) ? 68 : 256;
    const int tig = lane & 3, gid = lane >> 2;
    const int n  = nt * 8 + gid;
    const int k0 = kt * 16 + 2 * tig;

    float v[4];
#pragma unroll
    for (int r = 0; r < 4; r++){
        int k = k0 + (r >> 1) * 8 + (r & 1);         // k0, k0+1, k0+8, k0+9
        v[r] = (k < Kr) ? W[k * 256 + n] : 0.f;
    }
    uint32_t bh0, bl0, bh1, bl1;
    split2(v[0], v[1], bh0, bl0);
    split2(v[2], v[3], bh1, bl1);

    const size_t base = ((size_t)(((0*5 + l) * 16 + kt) * 32 + nt) * 32 + lane) * 2;
    const size_t pstep = (size_t)5*16*32*32*2;
    g_W[base]         = bh0;  g_W[base + 1]         = bh1;
    g_W[base + pstep] = bl0;  g_W[base + pstep + 1] = bl1;
}

// ---------------- main fused kernel ----------------
__global__ __launch_bounds__(NT, 2)
void drnfh_mma_kernel(const float* __restrict__ atoms,
                      const float* __restrict__ bonds,
                      const int*   __restrict__ edges,
                      const float* __restrict__ exist,
                      const float* __restrict__ b1, const float* __restrict__ b2,
                      const float* __restrict__ b3, const float* __restrict__ b4,
                      const float* __restrict__ b5,
                      const float* __restrict__ alphas, const float* __restrict__ betas,
                      float* __restrict__ out)
{
    extern __shared__ char smem[];
    const uint32_t sb = smem_u32(smem);
    float* hst = (float*)(smem + WBUF_OFF);         // h0 staging overlays W buffers

    const int tid  = threadIdx.x;
    const int lane = tid & 31;
    const int wid  = tid >> 5;
    const int wr   = wid >> 2;                      // warp row 0..1 (32 m-rows each)
    const int wc   = wid & 3;                       // warp col 0..3 (64 n-cols each)
    const int tig  = lane & 3;
    const int gid  = lane >> 2;
    const int t    = blockIdx.x;                    // 64-row tile; batch = t>>1

    // ---- build h0 fp32 (64 x 80, zero-padded) ----
    {
        const int batch = t >> 1;
        const int abase = (t & 1) * 64;
        const float* atom_b = atoms + (size_t)batch * 128 * 62;
        const float* bond_b = bonds + (size_t)batch * 128 * 30;
        const int*   edge_b = edges + (size_t)batch * 128 * 5;
        for (int idx = tid; idx < 64 * 80; idx += NT){
            const int r = idx / 80;
            const int f = idx - r * 80;
            const int a = abase + r;
            float v = 0.f;
            if (f < 62){
                v = atom_b[a * 62 + f];
#pragma unroll
                for (int d = 0; d < 5; d++){
                    const int e = edge_b[a * 5 + d];
                    if (e >= 0) v += atom_b[e * 62 + f];
                }
            } else if (f < 68){
                const int fb = f - 62;
#pragma unroll
                for (int d = 0; d < 5; d++)
                    v += bond_b[(a * 5 + d) * 6 + fb];
            }
            hst[r * HSTRIDE + f] = v;
        }
    }
    __syncthreads();

    // ---- split h0 into A fragment planes (mt 0..3, kt 0..4) ----
    for (int task = wid; task < 20; task += 8){
        const int mt = task / 5;
        const int kt = task - mt * 5;
        const int r0 = mt * 16 + gid;
        const int c0 = kt * 16 + 2 * tig;
        float2 x0 = *(const float2*)&hst[r0 * HSTRIDE + c0];
        float2 x1 = *(const float2*)&hst[(r0 + 8) * HSTRIDE + c0];
        float2 x2 = *(const float2*)&hst[r0 * HSTRIDE + c0 + 8];
        float2 x3 = *(const float2*)&hst[(r0 + 8) * HSTRIDE + c0 + 8];
        uint32_t ah[4], al[4];
        split2(x0.x, x0.y, ah[0], al[0]);
        split2(x1.x, x1.y, ah[1], al[1]);
        split2(x2.x, x2.y, ah[2], al[2]);
        split2(x3.x, x3.y, ah[3], al[3]);
        const uint32_t off = (uint32_t)(((mt * 16 + kt) * 32 + lane) * 16);
        STS128(sb + AHI_OFF + off, ah);
        STS128(sb + ALO_OFF + off, al);
    }
    __syncthreads();   // hst reads done; WBUF region reusable

    issue_chunk(0, sb, tid);
    issue_chunk(1, sb, tid);

    const float* bs[5] = { b1, b2, b3, b4, b5 };
    float acc[2][8][4];

    for (int g = 0; g < NCHUNK; g++){
        int l, kt; chunk_map(g, l, kt);

        if (g == NCHUNK - 1)
            asm volatile("cp.async.wait_group 0;" ::: "memory");
        else
            asm volatile("cp.async.wait_group 1;" ::: "memory");
        __syncthreads();
        if (g + 2 < NCHUNK) issue_chunk(g + 2, sb, tid);

        if (kt == 0){
#pragma unroll
            for (int i = 0; i < 2; i++)
#pragma unroll
                for (int j = 0; j < 8; j++)
#pragma unroll
                    for (int r = 0; r < 4; r++) acc[i][j][r] = 0.f;
        }

        const uint32_t wb = sb + WBUF_OFF + (uint32_t)(g % 3) * WBUF_SZ;

        // A fragments for this kt (2 mt rows per warp)
        uint32_t ah0[4], ah1[4], al0[4], al1[4];
        const uint32_t ao0 = (uint32_t)((((2*wr    ) * 16 + kt) * 32 + lane) * 16);
        const uint32_t ao1 = (uint32_t)((((2*wr + 1) * 16 + kt) * 32 + lane) * 16);
        LDS128(ah0, sb + AHI_OFF + ao0);
        LDS128(ah1, sb + AHI_OFF + ao1);
        LDS128(al0, sb + ALO_OFF + ao0);
        LDS128(al1, sb + ALO_OFF + ao1);

        uint32_t bt[16];
        // ---- B hi fragments, passes hh and lh (16 independent MMAs each) ----
#pragma unroll
        for (int j = 0; j < 8; j++){
            const uint32_t bo = (uint32_t)((((8*wc + j) * 32 + lane)) * 8);
            LDS64(bt[2*j], bt[2*j+1], wb + bo);
        }
#pragma unroll
        for (int j = 0; j < 8; j++){
            MMA(acc[0][j], ah0, bt[2*j], bt[2*j+1]);
            MMA(acc[1][j], ah1, bt[2*j], bt[2*j+1]);
        }
#pragma unroll
        for (int j = 0; j < 8; j++){
            MMA(acc[0][j], al0, bt[2*j], bt[2*j+1]);
            MMA(acc[1][j], al1, bt[2*j], bt[2*j+1]);
        }
        // ---- B lo fragments, pass hl ----
#pragma unroll
        for (int j = 0; j < 8; j++){
            const uint32_t bo = (uint32_t)(8192 + (((8*wc + j) * 32 + lane)) * 8);
            LDS64(bt[2*j], bt[2*j+1], wb + bo);
        }
#pragma unroll
        for (int j = 0; j < 8; j++){
            MMA(acc[0][j], ah0, bt[2*j], bt[2*j+1]);
            MMA(acc[1][j], ah1, bt[2*j], bt[2*j+1]);
        }

        const bool layer_end = (l == 0) ? (g == 4) : (((g - 5) & 15) == 15);
        if (layer_end){
            __syncthreads();   // all warps done reading A planes for this layer
            const float* bp = bs[l];
            const float a0 = __ldg(alphas + l*4 + 0), a1 = __ldg(alphas + l*4 + 1);
            const float a2 = __ldg(alphas + l*4 + 2), a3 = __ldg(alphas + l*4 + 3);
            const float q0 = __ldg(betas + l*3 + 0),  q1 = __ldg(betas + l*3 + 1);
            const float q2 = __ldg(betas + l*3 + 2);

            if (l < 4){
#pragma unroll
                for (int mt = 0; mt < 2; mt++){
#pragma unroll
                    for (int jj = 0; jj < 8; jj += 2){
                        float x[8];
#pragma unroll
                        for (int p = 0; p < 2; p++){
                            const int n0 = (8 * wc + jj + p) * 8 + 2 * tig;
                            const float2 bb = *(const float2*)(bp + n0);
                            x[p*4+0] = ract(acc[mt][jj+p][0] + bb.x, a0,a1,a2,a3, q0,q1,q2);
                            x[p*4+1] = ract(acc[mt][jj+p][1] + bb.y, a0,a1,a2,a3, q0,q1,q2);
                            x[p*4+2] = ract(acc[mt][jj+p][2] + bb.x, a0,a1,a2,a3, q0,q1,q2);
                            x[p*4+3] = ract(acc[mt][jj+p][3] + bb.y, a0,a1,a2,a3, q0,q1,q2);
                        }
                        uint32_t ah[4], al[4];
                        split2(x[0], x[1], ah[0], al[0]);   // (row gid,   cols 2tig..)
                        split2(x[2], x[3], ah[1], al[1]);   // (row gid+8)
                        split2(x[4], x[5], ah[2], al[2]);   // cols +8
                        split2(x[6], x[7], ah[3], al[3]);
                        const int ktn = 4 * wc + (jj >> 1);
                        const uint32_t off =
                            (uint32_t)((((2*wr + mt) * 16 + ktn) * 32 + lane) * 16);
                        STS128(sb + AHI_OFF + off, ah);
                        STS128(sb + ALO_OFF + off, al);
                    }
                }
                // next iteration's post-wait __syncthreads orders these writes
                // against next layer's A reads
            } else {
#pragma unroll
                for (int mt = 0; mt < 2; mt++){
                    const int r0 = (2*wr + mt) * 16 + gid;        // local row 0..63
                    const float e0 = exist[t * 64 + r0];
                    const float e1 = exist[t * 64 + r0 + 8];
#pragma unroll
                    for (int j = 0; j < 8; j++){
                        const int n0 = (8 * wc + j) * 8 + 2 * tig;
                        const float2 bb = *(const float2*)(bp + n0);
                        float y0 = ract(acc[mt][j][0] + bb.x, a0,a1,a2,a3, q0,q1,q2) * e0;
                        float y1 = ract(acc[mt][j][1] + bb.y, a0,a1,a2,a3, q0,q1,q2) * e0;
                        float y2 = ract(acc[mt][j][2] + bb.x, a0,a1,a2,a3, q0,q1,q2) * e1;
                        float y3 = ract(acc[mt][j][3] + bb.y, a0,a1,a2,a3, q0,q1,q2) * e1;
                        *(float2*)(out + ((size_t)t * 64 + r0) * 256 + n0)     = make_float2(y0, y1);
                        *(float2*)(out + ((size_t)t * 64 + r0 + 8) * 256 + n0) = make_float2(y2, y3);
                    }
                }
            }
        }
    }
}

extern "C" void kernel_launch(void* const* d_in, const int* in_sizes, int n_in,
                              void* d_out, int out_size)
{
    const float* atoms = (const float*)d_in[0];
    const float* bonds = (const float*)d_in[1];
    const int*   edges = (const int*)  d_in[2];
    const float* exist = (const float*)d_in[3];
    const float* W1 = (const float*)d_in[4];
    const float* b1 = (const float*)d_in[5];
    const float* W2 = (const float*)d_in[6];
    const float* b2 = (const float*)d_in[7];
    const float* W3 = (const float*)d_in[8];
    const float* b3 = (const float*)d_in[9];
    const float* W4 = (const float*)d_in[10];
    const float* b4 = (const float*)d_in[11];
    const float* W5 = (const float*)d_in[12];
    const float* b5 = (const float*)d_in[13];
    const float* alphas = (const float*)d_in[14];
    const float* betas  = (const float*)d_in[15];
    float* out = (float*)d_out;

    const int M = out_size / 256;     // 262144 rows
    const int T = M / 64;             // 4096 CTAs

    prep_kernel<<<(5*16*32*32 + 255) / 256, 256>>>(W1, W2, W3, W4, W5);

    cudaFuncSetAttribute(drnfh_mma_kernel,
                         cudaFuncAttributeMaxDynamicSharedMemorySize, SMEM_BYTES);
    drnfh_mma_kernel<<<T, NT, SMEM_BYTES>>>(
        atoms, bonds, edges, exist,
        b1, b2, b3, b4, b5, alphas, betas, out);
}

// round 7
// speedup vs baseline: 3.0756x; 1.0886x over previous
#include <cuda_runtime.h>
#include <cuda_bf16.h>
#include <cstdint>
#include <cstddef>

// Shapes fixed: B=2048, A=128, D=5, Fa=62, Fb=6, C=256, Fin=68 (pad K0 to 80)
// CTA tile: M=64, N=256; 8 warps, warp w covers all 64 rows x cols [32w, 32w+32).
#define NT 256

// dynamic smem layout (bytes)
#define AHI_OFF  0            // A hi plane: [4 mt][16 kt][32 lane][16B] = 32KB
#define ALO_OFF  32768        // A lo plane: 32KB
#define WBUF_OFF 65536        // per-warp: 8 x (3 buffers x 2KB) = 48KB
#define WARP_WSZ 6144
#define SMEM_BYTES (65536 + 8*WARP_WSZ)   // 114688 = 112KB -> 2 CTAs/SM
#define HSTRIDE 80            // h0 staging row stride (floats), overlays WBUF

#define NCHUNK 69             // layer0: 5 kt, layers1-4: 16 kt each

// weights in B-fragment order: [plane(hi/lo)][layer(5)][kt(16)][nt(32)][lane(32)][2 x u32]
__device__ __align__(16) uint32_t g_W[2*5*16*32*32*2];

// ---------------- helpers ----------------
static __device__ __forceinline__ uint32_t smem_u32(const void* p){
    uint32_t a;
    asm("{ .reg .u64 t; cvta.to.shared.u64 t, %1; cvt.u32.u64 %0, t; }" : "=r"(a) : "l"(p));
    return a;
}

static __device__ __forceinline__ void split2(float x, float y, uint32_t& h, uint32_t& l){
    asm("cvt.rn.bf16x2.f32 %0, %1, %2;" : "=r"(h) : "f"(y), "f"(x));
    float hx = __uint_as_float(h << 16);
    float hy = __uint_as_float(h & 0xffff0000u);
    float lx = x - hx, ly = y - hy;
    asm("cvt.rn.bf16x2.f32 %0, %1, %2;" : "=r"(l) : "f"(ly), "f"(lx));
}

#define MMA(d, a, b0, b1) \
    asm volatile("mma.sync.aligned.m16n8k16.row.col.f32.bf16.bf16.f32 " \
        "{%0,%1,%2,%3}, {%4,%5,%6,%7}, {%8,%9}, {%0,%1,%2,%3};" \
        : "+f"((d)[0]),"+f"((d)[1]),"+f"((d)[2]),"+f"((d)[3]) \
        : "r"((a)[0]),"r"((a)[1]),"r"((a)[2]),"r"((a)[3]), "r"(b0),"r"(b1))

#define LDS128(v, addr) \
    asm volatile("ld.shared.v4.b32 {%0,%1,%2,%3}, [%4];" \
        : "=r"((v)[0]),"=r"((v)[1]),"=r"((v)[2]),"=r"((v)[3]) : "r"(addr))

#define STS128(addr, v) \
    asm volatile("st.shared.v4.b32 [%0], {%1,%2,%3,%4};" \
        :: "r"(addr), "r"((v)[0]),"r"((v)[1]),"r"((v)[2]),"r"((v)[3]))

#define LDS64(b0, b1, addr) \
    asm volatile("ld.shared.v2.b32 {%0,%1}, [%2];" : "=r"(b0),"=r"(b1) : "r"(addr))

static __device__ __forceinline__ float ract(float x, float a0, float a1, float a2, float a3,
                                             float q0, float q1, float q2){
    float p = fmaf(fmaf(fmaf(a0, x, a1), x, a2), x, a3);
    float q = fmaf(fmaf(q0, x, q1), x, q2);    // q = 2.383 x^2 + 1 >= 1
    return __fdividef(p, q);
}

static __device__ __forceinline__ void chunk_map(int g, int& l, int& kt){
    if (g < 5){ l = 0; kt = g; }
    else { int r = g - 5; l = 1 + (r >> 4); kt = r & 15; }
}

// per-warp: fetch this warp's 2KB B chunk (hi+lo, 4 nt blocks) for chunk g
static __device__ __forceinline__ void issue_chunk(int g, uint32_t sb, int wid, int lane){
    int l, kt; chunk_map(g, l, kt);
    const uint32_t wb = sb + WBUF_OFF + (uint32_t)wid * WARP_WSZ + (uint32_t)(g % 3) * 2048;
    const char* gbase = (const char*)g_W;
#pragma unroll
    for (int i = 0; i < 4; i++){
        const int u = lane + 32 * i;           // 128 x 16B units
        const int plane = u >> 6;
        const int rem   = u & 63;
        const int nt    = rem >> 4;
        const int s     = rem & 15;
        const char* gp = gbase
            + ((size_t)((plane * 5 + l) * 16 + kt)) * 8192
            + (size_t)(4 * wid + nt) * 256 + s * 16;
        const uint32_t sp = wb + (uint32_t)((plane * 4 + nt) * 256 + s * 16);
        asm volatile("cp.async.ca.shared.global [%0], [%1], 16;" :: "r"(sp), "l"(gp));
    }
    asm volatile("cp.async.commit_group;" ::: "memory");
}

// ---------------- prep: W -> split bf16 B-fragment planes ----------------
__global__ void prep_kernel(const float* __restrict__ W1, const float* __restrict__ W2,
                            const float* __restrict__ W3, const float* __restrict__ W4,
                            const float* __restrict__ W5)
{
    int i = blockIdx.x * blockDim.x + threadIdx.x;   // 5*16*32*32 = 81920
    if (i >= 5*16*32*32) return;
    const int lane = i & 31;
    const int nt   = (i >> 5) & 31;
    const int kt   = (i >> 10) & 15;
    const int l    = i >> 14;
    const float* W = (l == 0) ? W1 : (l == 1) ? W2 : (l == 2) ? W3 : (l == 3) ? W4 : W5;
    const int Kr = (l == 0) ? 68 : 256;
    const int tig = lane & 3, gid = lane >> 2;
    const int n  = nt * 8 + gid;
    const int k0 = kt * 16 + 2 * tig;

    float v[4];
#pragma unroll
    for (int r = 0; r < 4; r++){
        int k = k0 + (r >> 1) * 8 + (r & 1);         // k0, k0+1, k0+8, k0+9
        v[r] = (k < Kr) ? W[k * 256 + n] : 0.f;
    }
    uint32_t bh0, bl0, bh1, bl1;
    split2(v[0], v[1], bh0, bl0);
    split2(v[2], v[3], bh1, bl1);

    const size_t base = ((size_t)(((0*5 + l) * 16 + kt) * 32 + nt) * 32 + lane) * 2;
    const size_t pstep = (size_t)5*16*32*32*2;
    g_W[base]         = bh0;  g_W[base + 1]         = bh1;
    g_W[base + pstep] = bl0;  g_W[base + pstep + 1] = bl1;
}

// ---------------- main fused kernel ----------------
__global__ __launch_bounds__(NT, 2)
void drnfh_mma_kernel(const float* __restrict__ atoms,
                      const float* __restrict__ bonds,
                      const int*   __restrict__ edges,
                      const float* __restrict__ exist,
                      const float* __restrict__ b1, const float* __restrict__ b2,
                      const float* __restrict__ b3, const float* __restrict__ b4,
                      const float* __restrict__ b5,
                      const float* __restrict__ alphas, const float* __restrict__ betas,
                      float* __restrict__ out)
{
    extern __shared__ char smem[];
    const uint32_t sb = smem_u32(smem);
    float* hst = (float*)(smem + WBUF_OFF);         // h0 staging overlays W buffers

    const int tid  = threadIdx.x;
    const int lane = tid & 31;
    const int wid  = tid >> 5;                      // warp 0..7 -> cols [32w, 32w+32)
    const int tig  = lane & 3;
    const int gid  = lane >> 2;
    const int t    = blockIdx.x;                    // 64-row tile; batch = t>>1

    // ---- build h0 fp32 (64 x 80, zero-padded) ----
    {
        const int batch = t >> 1;
        const int abase = (t & 1) * 64;
        const float* atom_b = atoms + (size_t)batch * 128 * 62;
        const float* bond_b = bonds + (size_t)batch * 128 * 30;
        const int*   edge_b = edges + (size_t)batch * 128 * 5;
        for (int idx = tid; idx < 64 * 80; idx += NT){
            const int r = idx / 80;
            const int f = idx - r * 80;
            const int a = abase + r;
            float v = 0.f;
            if (f < 62){
                v = atom_b[a * 62 + f];
#pragma unroll
                for (int d = 0; d < 5; d++){
                    const int e = edge_b[a * 5 + d];
                    if (e >= 0) v += atom_b[e * 62 + f];
                }
            } else if (f < 68){
                const int fb = f - 62;
#pragma unroll
                for (int d = 0; d < 5; d++)
                    v += bond_b[(a * 5 + d) * 6 + fb];
            }
            hst[r * HSTRIDE + f] = v;
        }
    }
    __syncthreads();

    // ---- split h0 into A fragment planes (mt 0..3, kt 0..4) ----
    for (int task = wid; task < 20; task += 8){
        const int mt = task / 5;
        const int kt = task - mt * 5;
        const int r0 = mt * 16 + gid;
        const int c0 = kt * 16 + 2 * tig;
        float2 x0 = *(const float2*)&hst[r0 * HSTRIDE + c0];
        float2 x1 = *(const float2*)&hst[(r0 + 8) * HSTRIDE + c0];
        float2 x2 = *(const float2*)&hst[r0 * HSTRIDE + c0 + 8];
        float2 x3 = *(const float2*)&hst[(r0 + 8) * HSTRIDE + c0 + 8];
        uint32_t ah[4], al[4];
        split2(x0.x, x0.y, ah[0], al[0]);
        split2(x1.x, x1.y, ah[1], al[1]);
        split2(x2.x, x2.y, ah[2], al[2]);
        split2(x3.x, x3.y, ah[3], al[3]);
        const uint32_t off = (uint32_t)(((mt * 16 + kt) * 32 + lane) * 16);
        STS128(sb + AHI_OFF + off, ah);
        STS128(sb + ALO_OFF + off, al);
    }
    __syncthreads();   // hst reads done; WBUF region reusable

    issue_chunk(0, sb, wid, lane);
    issue_chunk(1, sb, wid, lane);

    const float* bs[5] = { b1, b2, b3, b4, b5 };
    float acc[4][4][4];

    for (int g = 0; g < NCHUNK; g++){
        int l, kt; chunk_map(g, l, kt);

        if (g == NCHUNK - 1)
            asm volatile("cp.async.wait_group 0;" ::: "memory");
        else
            asm volatile("cp.async.wait_group 1;" ::: "memory");
        if (g + 2 < NCHUNK) issue_chunk(g + 2, sb, wid, lane);

        if (kt == 0){
#pragma unroll
            for (int i = 0; i < 4; i++)
#pragma unroll
                for (int j = 0; j < 4; j++)
#pragma unroll
                    for (int r = 0; r < 4; r++) acc[i][j][r] = 0.f;
        }

        const uint32_t wb = sb + WBUF_OFF + (uint32_t)wid * WARP_WSZ + (uint32_t)(g % 3) * 2048;

        // B hi fragments (this warp's 4 nt blocks)
        uint32_t bf[4][2];
#pragma unroll
        for (int nt = 0; nt < 4; nt++)
            LDS64(bf[nt][0], bf[nt][1], wb + (uint32_t)(nt * 256 + lane * 8));

        // A hi fragments (all 4 mt)
        uint32_t ah[4][4];
#pragma unroll
        for (int mt = 0; mt < 4; mt++)
            LDS128(ah[mt], sb + AHI_OFF + (uint32_t)(((mt * 16 + kt) * 32 + lane) * 16));

        // pass hh (16 independent MMAs)
#pragma unroll
        for (int mt = 0; mt < 4; mt++)
#pragma unroll
            for (int nt = 0; nt < 4; nt++)
                MMA(acc[mt][nt], ah[mt], bf[nt][0], bf[nt][1]);

        // A lo fragments; pass lh
        {
            uint32_t al[4][4];
#pragma unroll
            for (int mt = 0; mt < 4; mt++)
                LDS128(al[mt], sb + ALO_OFF + (uint32_t)(((mt * 16 + kt) * 32 + lane) * 16));
#pragma unroll
            for (int mt = 0; mt < 4; mt++)
#pragma unroll
                for (int nt = 0; nt < 4; nt++)
                    MMA(acc[mt][nt], al[mt], bf[nt][0], bf[nt][1]);
        }

        // B lo fragments (reuse bf regs); pass hl
#pragma unroll
        for (int nt = 0; nt < 4; nt++)
            LDS64(bf[nt][0], bf[nt][1], wb + (uint32_t)(1024 + nt * 256 + lane * 8));
#pragma unroll
        for (int mt = 0; mt < 4; mt++)
#pragma unroll
            for (int nt = 0; nt < 4; nt++)
                MMA(acc[mt][nt], ah[mt], bf[nt][0], bf[nt][1]);

        const bool layer_end = (l == 0) ? (g == 4) : (((g - 5) & 15) == 15);
        if (layer_end){
            __syncthreads();   // all warps done reading this layer's A planes
            const float* bp = bs[l];
            const float a0 = __ldg(alphas + l*4 + 0), a1 = __ldg(alphas + l*4 + 1);
            const float a2 = __ldg(alphas + l*4 + 2), a3 = __ldg(alphas + l*4 + 3);
            const float q0 = __ldg(betas + l*3 + 0),  q1 = __ldg(betas + l*3 + 1);
            const float q2 = __ldg(betas + l*3 + 2);

            if (l < 4){
#pragma unroll
                for (int mt = 0; mt < 4; mt++){
#pragma unroll
                    for (int jj = 0; jj < 4; jj += 2){
                        float x[8];
#pragma unroll
                        for (int p = 0; p < 2; p++){
                            const int n0 = (4 * wid + jj + p) * 8 + 2 * tig;
                            const float2 bb = *(const float2*)(bp + n0);
                            x[p*4+0] = ract(acc[mt][jj+p][0] + bb.x, a0,a1,a2,a3, q0,q1,q2);
                            x[p*4+1] = ract(acc[mt][jj+p][1] + bb.y, a0,a1,a2,a3, q0,q1,q2);
                            x[p*4+2] = ract(acc[mt][jj+p][2] + bb.x, a0,a1,a2,a3, q0,q1,q2);
                            x[p*4+3] = ract(acc[mt][jj+p][3] + bb.y, a0,a1,a2,a3, q0,q1,q2);
                        }
                        uint32_t ah2[4], al2[4];
                        split2(x[0], x[1], ah2[0], al2[0]);   // (row gid,   cols 2tig..)
                        split2(x[2], x[3], ah2[1], al2[1]);   // (row gid+8)
                        split2(x[4], x[5], ah2[2], al2[2]);   // cols +8
                        split2(x[6], x[7], ah2[3], al2[3]);
                        const int ktn = 2 * wid + (jj >> 1);
                        const uint32_t off =
                            (uint32_t)(((mt * 16 + ktn) * 32 + lane) * 16);
                        STS128(sb + AHI_OFF + off, ah2);
                        STS128(sb + ALO_OFF + off, al2);
                    }
                }
                __syncthreads();   // new A planes visible before next layer's reads
            } else {
#pragma unroll
                for (int mt = 0; mt < 4; mt++){
                    const int r0 = mt * 16 + gid;             // local row 0..63
                    const float e0 = exist[t * 64 + r0];
                    const float e1 = exist[t * 64 + r0 + 8];
#pragma unroll
                    for (int j = 0; j < 4; j++){
                        const int n0 = (4 * wid + j) * 8 + 2 * tig;
                        const float2 bb = *(const float2*)(bp + n0);
                        float y0 = ract(acc[mt][j][0] + bb.x, a0,a1,a2,a3, q0,q1,q2) * e0;
                        float y1 = ract(acc[mt][j][1] + bb.y, a0,a1,a2,a3, q0,q1,q2) * e0;
                        float y2 = ract(acc[mt][j][2] + bb.x, a0,a1,a2,a3, q0,q1,q2) * e1;
                        float y3 = ract(acc[mt][j][3] + bb.y, a0,a1,a2,a3, q0,q1,q2) * e1;
                        *(float2*)(out + ((size_t)t * 64 + r0) * 256 + n0)     = make_float2(y0, y1);
                        *(float2*)(out + ((size_t)t * 64 + r0 + 8) * 256 + n0) = make_float2(y2, y3);
                    }
                }
            }
        }
    }
}

extern "C" void kernel_launch(void* const* d_in, const int* in_sizes, int n_in,
                              void* d_out, int out_size)
{
    const float* atoms = (const float*)d_in[0];
    const float* bonds = (const float*)d_in[1];
    const int*   edges = (const int*)  d_in[2];
    const float* exist = (const float*)d_in[3];
    const float* W1 = (const float*)d_in[4];
    const float* b1 = (const float*)d_in[5];
    const float* W2 = (const float*)d_in[6];
    const float* b2 = (const float*)d_in[7];
    const float* W3 = (const float*)d_in[8];
    const float* b3 = (const float*)d_in[9];
    const float* W4 = (const float*)d_in[10];
    const float* b4 = (const float*)d_in[11];
    const float* W5 = (const float*)d_in[12];
    const float* b5 = (const float*)d_in[13];
    const float* alphas = (const float*)d_in[14];
    const float* betas  = (const float*)d_in[15];
    float* out = (float*)d_out;

    const int M = out_size / 256;     // 262144 rows
    const int T = M / 64;             // 4096 CTAs

    prep_kernel<<<(5*16*32*32 + 255) / 256, 256>>>(W1, W2, W3, W4, W5);

    cudaFuncSetAttribute(drnfh_mma_kernel,
                         cudaFuncAttributeMaxDynamicSharedMemorySize, SMEM_BYTES);
    drnfh_mma_kernel<<<T, NT, SMEM_BYTES>>>(
        atoms, bonds, edges, exist,
        b1, b2, b3, b4, b5, alphas, betas, out);
}

// round 9
// speedup vs baseline: 3.4138x; 1.1100x over previous
#include <cuda_runtime.h>
#include <cuda_bf16.h>
#include <cstdint>
#include <cstddef>

// Shapes fixed: B=2048, A=128, D=5, Fa=62, Fb=6, C=256, Fin=68 (pad K0 to 80)
// CTA tile: M=64, N=256; 8 warps, warp w covers all 64 rows x cols [32w, 32w+32).
#define NT 256

// dynamic smem layout (bytes)
#define AHI_OFF  0            // A hi plane: [4 mt][16 kt][32 lane][16B] = 32KB
#define ALO_OFF  32768        // A lo plane: 32KB
#define WBUF_OFF 65536        // per-warp: 8 x (3 buffers x 2KB) = 48KB
#define WARP_WSZ 6144
#define SMEM_BYTES (65536 + 8*WARP_WSZ)   // 114688 = 112KB -> 2 CTAs/SM
#define HSTRIDE 80            // h0 staging row stride (floats), overlays WBUF

#define NCHUNK 69             // layer0: 5 kt, layers1-4: 16 kt each

// weights, chunk-major: [chunk g(69)][warp(8)][plane(2)][ntl(4)][lane(32)][2 x u32] = 2KB/(g,warp)
__device__ __align__(16) uint32_t g_W2[NCHUNK*8*512];

// ---------------- helpers ----------------
static __device__ __forceinline__ uint32_t smem_u32(const void* p){
    uint32_t a;
    asm("{ .reg .u64 t; cvta.to.shared.u64 t, %1; cvt.u32.u64 %0, t; }" : "=r"(a) : "l"(p));
    return a;
}

static __device__ __forceinline__ void split2(float x, float y, uint32_t& h, uint32_t& l){
    asm("cvt.rn.bf16x2.f32 %0, %1, %2;" : "=r"(h) : "f"(y), "f"(x));
    float hx = __uint_as_float(h << 16);
    float hy = __uint_as_float(h & 0xffff0000u);
    float lx = x - hx, ly = y - hy;
    asm("cvt.rn.bf16x2.f32 %0, %1, %2;" : "=r"(l) : "f"(ly), "f"(lx));
}

#define MMA(d, a, b0, b1) \
    asm volatile("mma.sync.aligned.m16n8k16.row.col.f32.bf16.bf16.f32 " \
        "{%0,%1,%2,%3}, {%4,%5,%6,%7}, {%8,%9}, {%0,%1,%2,%3};" \
        : "+f"((d)[0]),"+f"((d)[1]),"+f"((d)[2]),"+f"((d)[3]) \
        : "r"((a)[0]),"r"((a)[1]),"r"((a)[2]),"r"((a)[3]), "r"(b0),"r"(b1))

#define LDS128(v, addr) \
    asm volatile("ld.shared.v4.b32 {%0,%1,%2,%3}, [%4];" \
        : "=r"((v)[0]),"=r"((v)[1]),"=r"((v)[2]),"=r"((v)[3]) : "r"(addr))

#define STS128(addr, v) \
    asm volatile("st.shared.v4.b32 [%0], {%1,%2,%3,%4};" \
        :: "r"(addr), "r"((v)[0]),"r"((v)[1]),"r"((v)[2]),"r"((v)[3]))

#define LDS64(b0, b1, addr) \
    asm volatile("ld.shared.v2.b32 {%0,%1}, [%2];" : "=r"(b0),"=r"(b1) : "r"(addr))

static __device__ __forceinline__ float ract(float x, float a0, float a1, float a2, float a3,
                                             float q0, float q1, float q2){
    float p = fmaf(fmaf(fmaf(a0, x, a1), x, a2), x, a3);
    float q = fmaf(fmaf(q0, x, q1), x, q2);    // q = 2.383 x^2 + 1 >= 1
    return __fdividef(p, q);
}

// per-warp: fetch this warp's 2KB B chunk for chunk g (single linear block)
static __device__ __forceinline__ void issue_chunk(int g, uint32_t sb, int wid, int lane){
    const uint32_t wb = sb + WBUF_OFF + (uint32_t)wid * WARP_WSZ
                      + (uint32_t)(g % 3) * 2048 + (uint32_t)lane * 16;
    const char* gp = (const char*)g_W2 + ((size_t)(g * 8 + wid)) * 2048 + (uint32_t)lane * 16;
#pragma unroll
    for (int i = 0; i < 4; i++)
        asm volatile("cp.async.ca.shared.global [%0], [%1], 16;"
                     :: "r"(wb + i * 512), "l"(gp + i * 512));
    asm volatile("cp.async.commit_group;" ::: "memory");
}

// ---------------- prep: W -> split bf16 B-fragment chunks ----------------
__global__ void prep_kernel(const float* __restrict__ W1, const float* __restrict__ W2,
                            const float* __restrict__ W3, const float* __restrict__ W4,
                            const float* __restrict__ W5)
{
    int i = blockIdx.x * blockDim.x + threadIdx.x;   // 5*16*32*32 = 81920
    if (i >= 5*16*32*32) return;
    const int lane = i & 31;
    const int nt   = (i >> 5) & 31;
    const int kt   = (i >> 10) & 15;
    const int l    = i >> 14;
    if (l == 0 && kt >= 5) return;                   // layer0 has only 5 kt chunks
    const float* W = (l == 0) ? W1 : (l == 1) ? W2 : (l == 2) ? W3 : (l == 3) ? W4 : W5;
    const int Kr = (l == 0) ? 68 : 256;
    const int tig = lane & 3, gid = lane >> 2;
    const int n  = nt * 8 + gid;
    const int k0 = kt * 16 + 2 * tig;

    float v[4];
#pragma unroll
    for (int r = 0; r < 4; r++){
        int k = k0 + (r >> 1) * 8 + (r & 1);         // k0, k0+1, k0+8, k0+9
        v[r] = (k < Kr) ? W[k * 256 + n] : 0.f;
    }
    uint32_t bh0, bl0, bh1, bl1;
    split2(v[0], v[1], bh0, bl0);
    split2(v[2], v[3], bh1, bl1);

    const int g   = (l == 0) ? kt : 5 + (l - 1) * 16 + kt;
    const int w   = nt >> 2;
    const int ntl = nt & 3;
    const size_t base = (size_t)(g * 8 + w) * 512 + (size_t)ntl * 64 + (size_t)lane * 2;
    g_W2[base]       = bh0;  g_W2[base + 1]       = bh1;   // plane hi (offset 0)
    g_W2[base + 256] = bl0;  g_W2[base + 257]     = bl1;   // plane lo (offset 1KB)
}

// ---------------- main fused kernel ----------------
__global__ __launch_bounds__(NT, 2)
void drnfh_mma_kernel(const float* __restrict__ atoms,
                      const float* __restrict__ bonds,
                      const int*   __restrict__ edges,
                      const float* __restrict__ exist,
                      const float* __restrict__ b1, const float* __restrict__ b2,
                      const float* __restrict__ b3, const float* __restrict__ b4,
                      const float* __restrict__ b5,
                      const float* __restrict__ alphas, const float* __restrict__ betas,
                      float* __restrict__ out)
{
    extern __shared__ char smem[];
    const uint32_t sb = smem_u32(smem);
    float* hst = (float*)(smem + WBUF_OFF);         // h0 staging overlays W buffers

    const int tid  = threadIdx.x;
    const int lane = tid & 31;
    const int wid  = tid >> 5;                      // warp 0..7 -> cols [32w, 32w+32)
    const int tig  = lane & 3;
    const int gid  = lane >> 2;
    const int t    = blockIdx.x;                    // 64-row tile; batch = t>>1

    // ---- build h0 fp32 (64 x 80, zero-padded) ----
    {
        const int batch = t >> 1;
        const int abase = (t & 1) * 64;
        const float* atom_b = atoms + (size_t)batch * 128 * 62;
        const float* bond_b = bonds + (size_t)batch * 128 * 30;
        const int*   edge_b = edges + (size_t)batch * 128 * 5;
        for (int idx = tid; idx < 64 * 80; idx += NT){
            const int r = idx / 80;
            const int f = idx - r * 80;
            const int a = abase + r;
            float v = 0.f;
            if (f < 62){
                v = atom_b[a * 62 + f];
#pragma unroll
                for (int d = 0; d < 5; d++){
                    const int e = edge_b[a * 5 + d];
                    if (e >= 0) v += atom_b[e * 62 + f];
                }
            } else if (f < 68){
                const int fb = f - 62;
#pragma unroll
                for (int d = 0; d < 5; d++)
                    v += bond_b[(a * 5 + d) * 6 + fb];
            }
            hst[r * HSTRIDE + f] = v;
        }
    }
    __syncthreads();

    // ---- split h0 into A fragment planes (mt 0..3, kt 0..4) ----
    for (int task = wid; task < 20; task += 8){
        const int mt = task / 5;
        const int kt = task - mt * 5;
        const int r0 = mt * 16 + gid;
        const int c0 = kt * 16 + 2 * tig;
        float2 x0 = *(const float2*)&hst[r0 * HSTRIDE + c0];
        float2 x1 = *(const float2*)&hst[(r0 + 8) * HSTRIDE + c0];
        float2 x2 = *(const float2*)&hst[r0 * HSTRIDE + c0 + 8];
        float2 x3 = *(const float2*)&hst[(r0 + 8) * HSTRIDE + c0 + 8];
        uint32_t ah[4], al[4];
        split2(x0.x, x0.y, ah[0], al[0]);
        split2(x1.x, x1.y, ah[1], al[1]);
        split2(x2.x, x2.y, ah[2], al[2]);
        split2(x3.x, x3.y, ah[3], al[3]);
        const uint32_t off = (uint32_t)(((mt * 16 + kt) * 32 + lane) * 16);
        STS128(sb + AHI_OFF + off, ah);
        STS128(sb + ALO_OFF + off, al);
    }
    __syncthreads();   // hst reads done; WBUF region reusable

    issue_chunk(0, sb, wid, lane);
    issue_chunk(1, sb, wid, lane);

    const float* bs[5] = { b1, b2, b3, b4, b5 };
    float acc[4][4][4];
    int g = 0;

#pragma unroll 1
    for (int l = 0; l < 5; l++){
        const int nkt = (l == 0) ? 5 : 16;

#pragma unroll
        for (int i = 0; i < 4; i++)
#pragma unroll
            for (int j = 0; j < 4; j++)
#pragma unroll
                for (int r = 0; r < 4; r++) acc[i][j][r] = 0.f;

#pragma unroll 1
        for (int kt = 0; kt < nkt; kt++, g++){
            if (g == NCHUNK - 1)
                asm volatile("cp.async.wait_group 0;" ::: "memory");
            else
                asm volatile("cp.async.wait_group 1;" ::: "memory");
            if (g + 2 < NCHUNK) issue_chunk(g + 2, sb, wid, lane);

            const uint32_t wb = sb + WBUF_OFF + (uint32_t)wid * WARP_WSZ
                              + (uint32_t)(g % 3) * 2048;
            const uint32_t ao = (uint32_t)(kt * 512 + lane * 16);

            // B hi fragments (4 nt blocks), A hi + A lo fragments (4 mt each)
            uint32_t bf[4][2];
#pragma unroll
            for (int nt = 0; nt < 4; nt++)
                LDS64(bf[nt][0], bf[nt][1], wb + (uint32_t)(nt * 256 + lane * 8));

            uint32_t ah[4][4], al[4][4];
#pragma unroll
            for (int mt = 0; mt < 4; mt++)
                LDS128(ah[mt], sb + AHI_OFF + ao + (uint32_t)(mt * 8192));
#pragma unroll
            for (int mt = 0; mt < 4; mt++)
                LDS128(al[mt], sb + ALO_OFF + ao + (uint32_t)(mt * 8192));

            // pass hh
#pragma unroll
            for (int mt = 0; mt < 4; mt++)
#pragma unroll
                for (int nt = 0; nt < 4; nt++)
                    MMA(acc[mt][nt], ah[mt], bf[nt][0], bf[nt][1]);
            // pass lh
#pragma unroll
            for (int mt = 0; mt < 4; mt++)
#pragma unroll
                for (int nt = 0; nt < 4; nt++)
                    MMA(acc[mt][nt], al[mt], bf[nt][0], bf[nt][1]);

            // B lo fragments (reuse regs); pass hl
#pragma unroll
            for (int nt = 0; nt < 4; nt++)
                LDS64(bf[nt][0], bf[nt][1], wb + (uint32_t)(1024 + nt * 256 + lane * 8));
#pragma unroll
            for (int mt = 0; mt < 4; mt++)
#pragma unroll
                for (int nt = 0; nt < 4; nt++)
                    MMA(acc[mt][nt], ah[mt], bf[nt][0], bf[nt][1]);
        }

        // ---- layer epilogue ----
        __syncthreads();   // all warps done reading this layer's A planes
        const float* bp = bs[l];
        const float a0 = __ldg(alphas + l*4 + 0), a1 = __ldg(alphas + l*4 + 1);
        const float a2 = __ldg(alphas + l*4 + 2), a3 = __ldg(alphas + l*4 + 3);
        const float q0 = __ldg(betas + l*3 + 0),  q1 = __ldg(betas + l*3 + 1);
        const float q2 = __ldg(betas + l*3 + 2);

        if (l < 4){
#pragma unroll
            for (int mt = 0; mt < 4; mt++){
#pragma unroll
                for (int jj = 0; jj < 4; jj += 2){
                    float x[8];
#pragma unroll
                    for (int p = 0; p < 2; p++){
                        const int n0 = (4 * wid + jj + p) * 8 + 2 * tig;
                        const float2 bb = *(const float2*)(bp + n0);
                        x[p*4+0] = ract(acc[mt][jj+p][0] + bb.x, a0,a1,a2,a3, q0,q1,q2);
                        x[p*4+1] = ract(acc[mt][jj+p][1] + bb.y, a0,a1,a2,a3, q0,q1,q2);
                        x[p*4+2] = ract(acc[mt][jj+p][2] + bb.x, a0,a1,a2,a3, q0,q1,q2);
                        x[p*4+3] = ract(acc[mt][jj+p][3] + bb.y, a0,a1,a2,a3, q0,q1,q2);
                    }
                    uint32_t ah2[4], al2[4];
                    split2(x[0], x[1], ah2[0], al2[0]);   // (row gid,   cols 2tig..)
                    split2(x[2], x[3], ah2[1], al2[1]);   // (row gid+8)
                    split2(x[4], x[5], ah2[2], al2[2]);   // cols +8
                    split2(x[6], x[7], ah2[3], al2[3]);
                    const int ktn = 2 * wid + (jj >> 1);
                    const uint32_t off =
                        (uint32_t)(((mt * 16 + ktn) * 32 + lane) * 16);
                    STS128(sb + AHI_OFF + off, ah2);
                    STS128(sb + ALO_OFF + off, al2);
                }
            }
            __syncthreads();   // new A planes visible before next layer's reads
        } else {
#pragma unroll
            for (int mt = 0; mt < 4; mt++){
                const int r0 = mt * 16 + gid;             // local row 0..63
                const float e0 = exist[t * 64 + r0];
                const float e1 = exist[t * 64 + r0 + 8];
#pragma unroll
                for (int j = 0; j < 4; j++){
                    const int n0 = (4 * wid + j) * 8 + 2 * tig;
                    const float2 bb = *(const float2*)(bp + n0);
                    float y0 = ract(acc[mt][j][0] + bb.x, a0,a1,a2,a3, q0,q1,q2) * e0;
                    float y1 = ract(acc[mt][j][1] + bb.y, a0,a1,a2,a3, q0,q1,q2) * e0;
                    float y2 = ract(acc[mt][j][2] + bb.x, a0,a1,a2,a3, q0,q1,q2) * e1;
                    float y3 = ract(acc[mt][j][3] + bb.y, a0,a1,a2,a3, q0,q1,q2) * e1;
                    *(float2*)(out + ((size_t)t * 64 + r0) * 256 + n0)     = make_float2(y0, y1);
                    *(float2*)(out + ((size_t)t * 64 + r0 + 8) * 256 + n0) = make_float2(y2, y3);
                }
            }
        }
    }
}

extern "C" void kernel_launch(void* const* d_in, const int* in_sizes, int n_in,
                              void* d_out, int out_size)
{
    const float* atoms = (const float*)d_in[0];
    const float* bonds = (const float*)d_in[1];
    const int*   edges = (const int*)  d_in[2];
    const float* exist = (const float*)d_in[3];
    const float* W1 = (const float*)d_in[4];
    const float* b1 = (const float*)d_in[5];
    const float* W2 = (const float*)d_in[6];
    const float* b2 = (const float*)d_in[7];
    const float* W3 = (const float*)d_in[8];
    const float* b3 = (const float*)d_in[9];
    const float* W4 = (const float*)d_in[10];
    const float* b4 = (const float*)d_in[11];
    const float* W5 = (const float*)d_in[12];
    const float* b5 = (const float*)d_in[13];
    const float* alphas = (const float*)d_in[14];
    const float* betas  = (const float*)d_in[15];
    float* out = (float*)d_out;

    const int M = out_size / 256;     // 262144 rows
    const int T = M / 64;             // 4096 CTAs

    prep_kernel<<<(5*16*32*32 + 255) / 256, 256>>>(W1, W2, W3, W4, W5);

    cudaFuncSetAttribute(drnfh_mma_kernel,
                         cudaFuncAttributeMaxDynamicSharedMemorySize, SMEM_BYTES);
    drnfh_mma_kernel<<<T, NT, SMEM_BYTES>>>(
        atoms, bonds, edges, exist,
        b1, b2, b3, b4, b5, alphas, betas, out);
}